// round 14
// baseline (speedup 1.0000x reference)
#include <cuda_runtime.h>
#include <cuda_fp16.h>
#include <cstdint>

// NT-Xent loss. N=4096 (concat z_i,z_j), D=256, C=100.
// All-int8 scheme, S = 98304:
//   q = round(S*x) = 256*a1 + a2  (a1,a2 in s8)
//   sim ~= [65536*(a1.a1') + 256*(a1.a2' + a2.a1')] / S^2   (a2.a2' dropped)
// 384 IMMA per warp-tile. Packed row g_pk[4096][1024B] = [a1|a2|unused].
// 6 K-chunks of 128B/row, MAIN FIRST then CROSS so only ONE s32 accumulator
// set is ever live next to the f32 accumulator -> ~84 regs -> 3 CTAs/SM
// (r13 ncu: tensor 23.8%, occ 22.9% -> latency-bound; occupancy is the lever).
//   chunks 0-1: main (a1,a1); chunks 2-5: cross (A=[a1|a2], B=[a2|a1]).
// Tiles 128x128 triangular br<=bc (528); element (gr,gc) counted iff gr<gc,
// scattered to both sides. 256 threads, 2-stage cp.async.
// Final reduction fused into k_sim via completion counter (last CTA).

#define BATCH 2048
#define N_TOT 4096
#define TS    128
#define NTILE (N_TOT / TS)                // 32
#define NTILES (NTILE * (NTILE + 1) / 2)  // 528
#define NCH   6                           // chunks of 128B/row
#define SROWB 144                         // smem row stride (9*16B, conflict-free)
#define A_STG (TS * SROWB)                // 18432
#define B_STG (TS * SROWB)                // 18432
#define B_OFF (2 * A_STG)                 // 36864
#define SMEM_DYN (2 * A_STG + 2 * B_STG)  // 73728
// S = 98304; S^2 = 9663676416
#define KC1 (256.0f / 9663676416.0f)      // cross-term scale
#define KC2 (65536.0f / 9663676416.0f)    // main-term scale

__device__ __align__(16) unsigned char g_pk[(size_t)N_TOT * 1024];  // 4MB
__device__ int   g_lab[N_TOT];
__device__ float g_den[N_TOT];
__device__ float g_nom[N_TOT];
__device__ int   g_ctr;                   // completion counter (reset by last CTA)

// ---------------------------------------------------------------------------
__device__ __forceinline__ uint32_t smem_u32(const void* p) {
    uint32_t a;
    asm("{ .reg .u64 t; cvta.to.shared.u64 t, %1; cvt.u32.u64 %0, t; }" : "=r"(a) : "l"(p));
    return a;
}
#define LDSM_X4(r0, r1, r2, r3, addr) \
    asm volatile("ldmatrix.sync.aligned.m8n8.x4.shared.b16 {%0,%1,%2,%3}, [%4];" \
                 : "=r"(r0), "=r"(r1), "=r"(r2), "=r"(r3) : "r"(addr))
__device__ __forceinline__ void cp_async16(uint32_t dst, const void* src) {
    asm volatile("cp.async.cg.shared.global [%0], [%1], 16;" :: "r"(dst), "l"(src));
}
#define CP_COMMIT() asm volatile("cp.async.commit_group;" ::: "memory")
#define CP_WAIT1()  asm volatile("cp.async.wait_group 1;" ::: "memory")

__device__ __forceinline__ void imma_s8(int* d, const uint32_t* a,
                                        uint32_t b0, uint32_t b1) {
    asm volatile("mma.sync.aligned.m16n8k32.row.col.s32.s8.s8.s32 "
                 "{%0,%1,%2,%3}, {%4,%5,%6,%7}, {%8,%9}, {%0,%1,%2,%3};"
                 : "+r"(d[0]), "+r"(d[1]), "+r"(d[2]), "+r"(d[3])
                 : "r"(a[0]), "r"(a[1]), "r"(a[2]), "r"(a[3]), "r"(b0), "r"(b1));
}

// exp(x) on [-1,1], degree-9 Taylor (Horner). |abs err| < 3e-7, fma pipe only.
__device__ __forceinline__ float exp_poly(float x) {
    float p = 2.7557319e-6f;
    p = fmaf(p, x, 2.4801587e-5f);
    p = fmaf(p, x, 1.9841270e-4f);
    p = fmaf(p, x, 1.3888889e-3f);
    p = fmaf(p, x, 8.3333333e-3f);
    p = fmaf(p, x, 4.1666667e-2f);
    p = fmaf(p, x, 1.6666667e-1f);
    p = fmaf(p, x, 0.5f);
    p = fmaf(p, x, 1.0f);
    p = fmaf(p, x, 1.0f);
    return p;
}

// ---------------------------------------------------------------------------
// Prep: 512 blocks x 256 threads; one warp per row, no smem, no syncthreads.
__global__ void k_prep(const float* __restrict__ zi,
                       const float* __restrict__ zj,
                       const float* __restrict__ dist) {
    int lane = threadIdx.x & 31;
    int w    = threadIdx.x >> 5;
    int row  = blockIdx.x * 8 + w;
    int srow = (row < BATCH) ? row : row - BATCH;
    const float* src = ((row < BATCH) ? zi : zj) + (size_t)srow * 256;

    float4 v0 = ((const float4*)src)[lane];
    float4 v1 = ((const float4*)src)[lane + 32];
    float ss = v0.x * v0.x + v0.y * v0.y + v0.z * v0.z + v0.w * v0.w
             + v1.x * v1.x + v1.y * v1.y + v1.z * v1.z + v1.w * v1.w;
    #pragma unroll
    for (int o = 16; o; o >>= 1) ss += __shfl_xor_sync(0xffffffffu, ss, o);
    float rn = 1.0f / sqrtf(ss);

    // one-hot label scan (coalesced, warp-parallel, max-reduce)
    const float* dr = dist + (size_t)srow * 100;
    int cand = -1;
    if (dr[lane] > 0.5f)      cand = lane;
    if (dr[lane + 32] > 0.5f) cand = lane + 32;
    if (dr[lane + 64] > 0.5f) cand = lane + 64;
    if (lane < 4 && dr[lane + 96] > 0.5f) cand = lane + 96;
    #pragma unroll
    for (int o = 16; o; o >>= 1) cand = max(cand, __shfl_xor_sync(0xffffffffu, cand, o));

    // quantize 8 elements: q = round(S*x) = 256*a1 + a2
    float x[8] = {v0.x * rn, v0.y * rn, v0.z * rn, v0.w * rn,
                  v1.x * rn, v1.y * rn, v1.z * rn, v1.w * rn};
    signed char a1[8], a2[8];
    #pragma unroll
    for (int i = 0; i < 8; i++) {
        int q = __float2int_rn(x[i] * 98304.0f);
        q = max(-32639, min(32639, q));    // a1 in [-127,127], a2 in [-128,127]
        int h = (q + 128) >> 8;
        a1[i] = (signed char)h;
        a2[i] = (signed char)(q - (h << 8));
    }
    unsigned char* pr = g_pk + (size_t)row * 1024;
    *(char4*)(pr + lane * 4)             = make_char4(a1[0], a1[1], a1[2], a1[3]);
    *(char4*)(pr + 128 + lane * 4)       = make_char4(a1[4], a1[5], a1[6], a1[7]);
    *(char4*)(pr + 256 + lane * 4)       = make_char4(a2[0], a2[1], a2[2], a2[3]);
    *(char4*)(pr + 384 + lane * 4)       = make_char4(a2[4], a2[5], a2[6], a2[7]);

    if (lane == 0) {
        g_lab[row] = cand;
        g_den[row] = 0.f;
        g_nom[row] = 0.f;
    }
}

// ---------------------------------------------------------------------------
// k_sim: one 128x128 tile per CTA. 8 warps (4 over M x 2 over N), 32x64/warp.
// 3 CTAs/SM (launch_bounds caps regs ~84). Last CTA does the final reduction.
__global__ void __launch_bounds__(256, 3) k_sim(float* __restrict__ out) {
    extern __shared__ char sm[];
    __shared__ int sLabR[TS], sLabC[TS];
    __shared__ int sLast;
    __shared__ float fpart[8];

    int tid  = threadIdx.x;
    int lane = tid & 31;
    int wid  = tid >> 5;
    int wm   = wid & 3;           // 4 warps over M (32 rows each)
    int wn   = wid >> 2;          // 2 warps over N (64 cols each)

    // decode linear tile id -> (br, bc) with bc >= br (triangular)
    int t = blockIdx.x;
    int br = 0;
    while (t >= (NTILE - br)) { t -= (NTILE - br); br++; }
    int bc = br + t;
    int rowA0 = br * TS;
    int rowB0 = bc * TS;

    if (tid < TS) {
        sLabR[tid] = g_lab[rowA0 + tid];
        sLabC[tid] = g_lab[rowB0 + tid];
    }

    uint32_t smB = smem_u32(sm);

    // chunk -> source byte offsets in the packed row
    // main  (c 0..1): both a1 -> 0,128
    // cross (c 2..5): A = [a1|a2] -> 0,128,256,384 ; B = [a2|a1] -> 256,384,0,128
    auto srcOffA = [](int c) { return (c < 2) ? c * 128 : (c - 2) * 128; };
    auto srcOffB = [](int c) {
        return (c < 2) ? c * 128
             : ((c < 4) ? (c - 2) * 128 + 256 : (c - 4) * 128);
    };

    auto issue = [&](int c, int st) {
        int oA = srcOffA(c), oB = srcOffB(c);
        #pragma unroll
        for (int u = 0; u < 4; u++) {                 // A: 1024 x 16B
            int idx = tid + u * 256, r = idx >> 3, ks = idx & 7;
            cp_async16(smB + st * A_STG + r * SROWB + ks * 16,
                       g_pk + (size_t)(rowA0 + r) * 1024 + oA + ks * 16);
        }
        #pragma unroll
        for (int u = 0; u < 4; u++) {                 // B: 1024 x 16B
            int idx = tid + u * 256, r = idx >> 3, ks = idx & 7;
            cp_async16(smB + B_OFF + st * B_STG + r * SROWB + ks * 16,
                       g_pk + (size_t)(rowB0 + r) * 1024 + oB + ks * 16);
        }
        CP_COMMIT();
    };

    int acc[2][8][4];             // the ONLY s32 accumulator set
    #pragma unroll
    for (int i = 0; i < 2; i++)
        #pragma unroll
        for (int j = 0; j < 8; j++)
            #pragma unroll
            for (int k = 0; k < 4; k++) acc[i][j][k] = 0;

    issue(0, 0);
    issue(1, 1);

    uint32_t aLane = (uint32_t)((wm * 32 + (lane & 15)) * SROWB + (lane >> 4) * 16);
    uint32_t bLane = (uint32_t)(B_OFF + (wn * 64 + (lane & 15)) * SROWB + (lane >> 4) * 16);

    // ---- phase 1: main product a1.a1', chunks 0..1 ----
    #pragma unroll 1
    for (int c = 0; c < 2; c++) {
        int st = c & 1;
        CP_WAIT1();
        __syncthreads();

        uint32_t aBase = smB + st * A_STG + aLane;
        uint32_t bBase = smB + st * B_STG + bLane;
        #pragma unroll
        for (int ks = 0; ks < 4; ks++) {
            uint32_t A[2][4];
            #pragma unroll
            for (int mt = 0; mt < 2; mt++)
                LDSM_X4(A[mt][0], A[mt][1], A[mt][2], A[mt][3],
                        aBase + mt * 16 * SROWB + ks * 32);
            #pragma unroll
            for (int ntp = 0; ntp < 4; ntp++) {
                uint32_t b[4];
                LDSM_X4(b[0], b[1], b[2], b[3], bBase + ntp * 16 * SROWB + ks * 32);
                #pragma unroll
                for (int mt = 0; mt < 2; mt++) {
                    imma_s8(acc[mt][ntp * 2],     A[mt], b[0], b[2]);
                    imma_s8(acc[mt][ntp * 2 + 1], A[mt], b[1], b[3]);
                }
            }
        }
        __syncthreads();
        issue(c + 2, st);
    }

    // ---- fold main: exact s32 -> f32 (|S| <= 4.2e6 < 2^23); reset acc ----
    float accf[2][8][4];
    #pragma unroll
    for (int i = 0; i < 2; i++)
        #pragma unroll
        for (int j = 0; j < 8; j++)
            #pragma unroll
            for (int k = 0; k < 4; k++) {
                accf[i][j][k] = (float)acc[i][j][k] * KC2;
                acc[i][j][k] = 0;
            }

    // ---- phase 2: cross terms a1.a2' + a2.a1', chunks 2..5 ----
    #pragma unroll 1
    for (int c = 2; c < NCH; c++) {
        int st = c & 1;
        CP_WAIT1();
        __syncthreads();

        uint32_t aBase = smB + st * A_STG + aLane;
        uint32_t bBase = smB + st * B_STG + bLane;
        #pragma unroll
        for (int ks = 0; ks < 4; ks++) {
            uint32_t A[2][4];
            #pragma unroll
            for (int mt = 0; mt < 2; mt++)
                LDSM_X4(A[mt][0], A[mt][1], A[mt][2], A[mt][3],
                        aBase + mt * 16 * SROWB + ks * 32);
            #pragma unroll
            for (int ntp = 0; ntp < 4; ntp++) {
                uint32_t b[4];
                LDSM_X4(b[0], b[1], b[2], b[3], bBase + ntp * 16 * SROWB + ks * 32);
                #pragma unroll
                for (int mt = 0; mt < 2; mt++) {
                    imma_s8(acc[mt][ntp * 2],     A[mt], b[0], b[2]);
                    imma_s8(acc[mt][ntp * 2 + 1], A[mt], b[1], b[3]);
                }
            }
        }
        __syncthreads();
        if (c + 2 < NCH) issue(c + 2, st);
        else CP_COMMIT();
    }

    // ---- fold cross: exact s32 -> f32 (|S| <= 8.4e6 < 2^23) ----
    #pragma unroll
    for (int i = 0; i < 2; i++)
        #pragma unroll
        for (int j = 0; j < 8; j++)
            #pragma unroll
            for (int k = 0; k < 4; k++)
                accf[i][j][k] = fmaf((float)acc[i][j][k], KC1, accf[i][j][k]);

    // ---------------- epilogue: count (gr,gc) iff gr<gc, scatter both sides --
    int mrow = lane >> 2;
    int ncol = (lane & 3) * 2;

    float cd[8][2], cm[8][2];
    #pragma unroll
    for (int n8 = 0; n8 < 8; n8++) { cd[n8][0] = cd[n8][1] = 0.f; cm[n8][0] = cm[n8][1] = 0.f; }

    #pragma unroll
    for (int mt = 0; mt < 2; mt++) {
        #pragma unroll
        for (int h = 0; h < 2; h++) {
            int rloc = wm * 32 + mt * 16 + h * 8 + mrow;
            int gr   = rowA0 + rloc;
            int labr = sLabR[rloc];
            float rd = 0.f, rm = 0.f;
            #pragma unroll
            for (int n8 = 0; n8 < 8; n8++) {
                #pragma unroll
                for (int j = 0; j < 2; j++) {
                    int cloc = wn * 64 + n8 * 8 + ncol + j;
                    int gc   = rowB0 + cloc;
                    float s  = accf[mt][n8][h * 2 + j];
                    if (gr < gc) {
                        float e = exp_poly(s);
                        float m = (labr == sLabC[cloc]) ? s : 0.f;
                        rd += e; rm += m;
                        cd[n8][j] += e; cm[n8][j] += m;
                    }
                }
            }
            #pragma unroll
            for (int o = 1; o <= 2; o <<= 1) {
                rd += __shfl_xor_sync(0xffffffffu, rd, o);
                rm += __shfl_xor_sync(0xffffffffu, rm, o);
            }
            if ((lane & 3) == 0) {
                atomicAdd(&g_den[gr], rd);
                atomicAdd(&g_nom[gr], rm);
            }
        }
    }
    #pragma unroll
    for (int n8 = 0; n8 < 8; n8++)
        #pragma unroll
        for (int j = 0; j < 2; j++) {
            #pragma unroll
            for (int o = 4; o <= 16; o <<= 1) {
                cd[n8][j] += __shfl_xor_sync(0xffffffffu, cd[n8][j], o);
                cm[n8][j] += __shfl_xor_sync(0xffffffffu, cm[n8][j], o);
            }
            if (lane < 4) {
                int gc = rowB0 + wn * 64 + n8 * 8 + (lane & 3) * 2 + j;
                atomicAdd(&g_den[gc], cd[n8][j]);
                atomicAdd(&g_nom[gc], cm[n8][j]);
            }
        }

    // ---------------- fused final reduction (last CTA) ----------------------
    __threadfence();              // make this CTA's atomics globally visible
    __syncthreads();
    if (tid == 0) {
        int prev = atomicAdd(&g_ctr, 1);
        sLast = (prev == NTILES - 1) ? 1 : 0;
    }
    __syncthreads();
    if (sLast) {
        __threadfence();
        float s = 0.f;
        #pragma unroll
        for (int i = 0; i < 16; i++) {
            int n = tid + i * 256;
            s += g_nom[n] / g_den[n];
        }
        #pragma unroll
        for (int o = 16; o; o >>= 1) s += __shfl_xor_sync(0xffffffffu, s, o);
        if (lane == 0) fpart[wid] = s;
        __syncthreads();
        if (tid == 0) {
            float tot = 0.f;
            #pragma unroll
            for (int i = 0; i < 8; i++) tot += fpart[i];
            out[0] = tot / 4096.0f;
            g_ctr = 0;            // reset for next graph replay
        }
    }
}

// ---------------------------------------------------------------------------
extern "C" void kernel_launch(void* const* d_in, const int* in_sizes, int n_in,
                              void* d_out, int out_size) {
    const float* zi   = (const float*)d_in[0];
    const float* zj   = (const float*)d_in[1];
    // d_in[2] = z_n is dead code in the reference
    const float* dist = (const float*)d_in[3];
    float* out = (float*)d_out;

    cudaFuncSetAttribute(k_sim, cudaFuncAttributeMaxDynamicSharedMemorySize, SMEM_DYN);

    k_prep<<<512, 256>>>(zi, zj, dist);
    k_sim<<<NTILES, 256, SMEM_DYN>>>(out);
}

// round 15
// speedup vs baseline: 1.8093x; 1.8093x over previous
#include <cuda_runtime.h>
#include <cuda_fp16.h>
#include <cstdint>

// NT-Xent loss. N=4096 (concat z_i,z_j), D=256, C=100.
// All-int8 scheme, S = 98304:
//   q = round(S*x) = 256*a1 + a2  (a1,a2 in s8)
//   sim ~= [65536*(a1.a1') + 256*(a1.a2' + a2.a1')] / S^2   (a2.a2' dropped)
// Packed row g_pk[4096][1024B] = [a1|a2|unused].
// 6 K-chunks of 128B/row, MAIN FIRST (c 0-1: a1,a1) then CROSS (c 2-5:
// A=[a1|a2], B=[a2|a1]) so only ONE s32 accumulator set is live.
// Tiles 128x128 triangular br<=bc (528); element (gr,gc) counted iff gr<gc,
// scattered to both sides.
// k_sim: 512 threads, 16 warps = 4 M x 4 N of 32x32 -> 32 acc regs/thread,
// ~60 live regs -> launch_bounds(512,2) with NO spill -> 50% occupancy
// (r13: 128 regs, 22.9% occ, tensor 23.8% -> latency-bound; r14 showed caps
// below the live set spill catastrophically -- this shrinks the live set).
// 2-stage cp.async; fused last-CTA final reduction.

#define BATCH 2048
#define N_TOT 4096
#define TS    128
#define NTILE (N_TOT / TS)                // 32
#define NTILES (NTILE * (NTILE + 1) / 2)  // 528
#define NCH   6                           // chunks of 128B/row
#define SROWB 144                         // smem row stride (9*16B, conflict-free)
#define A_STG (TS * SROWB)                // 18432
#define B_STG (TS * SROWB)                // 18432
#define B_OFF (2 * A_STG)                 // 36864
#define SMEM_DYN (2 * A_STG + 2 * B_STG)  // 73728
// S = 98304; S^2 = 9663676416
#define KC1 (256.0f / 9663676416.0f)      // cross-term scale
#define KC2 (65536.0f / 9663676416.0f)    // main-term scale

__device__ __align__(16) unsigned char g_pk[(size_t)N_TOT * 1024];  // 4MB
__device__ int   g_lab[N_TOT];
__device__ float g_den[N_TOT];
__device__ float g_nom[N_TOT];
__device__ int   g_ctr;                   // completion counter (reset by last CTA)

// ---------------------------------------------------------------------------
__device__ __forceinline__ uint32_t smem_u32(const void* p) {
    uint32_t a;
    asm("{ .reg .u64 t; cvta.to.shared.u64 t, %1; cvt.u32.u64 %0, t; }" : "=r"(a) : "l"(p));
    return a;
}
#define LDSM_X4(r0, r1, r2, r3, addr) \
    asm volatile("ldmatrix.sync.aligned.m8n8.x4.shared.b16 {%0,%1,%2,%3}, [%4];" \
                 : "=r"(r0), "=r"(r1), "=r"(r2), "=r"(r3) : "r"(addr))
__device__ __forceinline__ void cp_async16(uint32_t dst, const void* src) {
    asm volatile("cp.async.cg.shared.global [%0], [%1], 16;" :: "r"(dst), "l"(src));
}
#define CP_COMMIT() asm volatile("cp.async.commit_group;" ::: "memory")
#define CP_WAIT1()  asm volatile("cp.async.wait_group 1;" ::: "memory")

__device__ __forceinline__ void imma_s8(int* d, const uint32_t* a,
                                        uint32_t b0, uint32_t b1) {
    asm volatile("mma.sync.aligned.m16n8k32.row.col.s32.s8.s8.s32 "
                 "{%0,%1,%2,%3}, {%4,%5,%6,%7}, {%8,%9}, {%0,%1,%2,%3};"
                 : "+r"(d[0]), "+r"(d[1]), "+r"(d[2]), "+r"(d[3])
                 : "r"(a[0]), "r"(a[1]), "r"(a[2]), "r"(a[3]), "r"(b0), "r"(b1));
}

// exp(x) on [-1,1], degree-9 Taylor (Horner). |abs err| < 3e-7, fma pipe only.
__device__ __forceinline__ float exp_poly(float x) {
    float p = 2.7557319e-6f;
    p = fmaf(p, x, 2.4801587e-5f);
    p = fmaf(p, x, 1.9841270e-4f);
    p = fmaf(p, x, 1.3888889e-3f);
    p = fmaf(p, x, 8.3333333e-3f);
    p = fmaf(p, x, 4.1666667e-2f);
    p = fmaf(p, x, 1.6666667e-1f);
    p = fmaf(p, x, 0.5f);
    p = fmaf(p, x, 1.0f);
    p = fmaf(p, x, 1.0f);
    return p;
}

// ---------------------------------------------------------------------------
// Prep: 512 blocks x 256 threads; one warp per row, no smem, no syncthreads.
__global__ void k_prep(const float* __restrict__ zi,
                       const float* __restrict__ zj,
                       const float* __restrict__ dist) {
    int lane = threadIdx.x & 31;
    int w    = threadIdx.x >> 5;
    int row  = blockIdx.x * 8 + w;
    int srow = (row < BATCH) ? row : row - BATCH;
    const float* src = ((row < BATCH) ? zi : zj) + (size_t)srow * 256;

    float4 v0 = ((const float4*)src)[lane];
    float4 v1 = ((const float4*)src)[lane + 32];
    float ss = v0.x * v0.x + v0.y * v0.y + v0.z * v0.z + v0.w * v0.w
             + v1.x * v1.x + v1.y * v1.y + v1.z * v1.z + v1.w * v1.w;
    #pragma unroll
    for (int o = 16; o; o >>= 1) ss += __shfl_xor_sync(0xffffffffu, ss, o);
    float rn = 1.0f / sqrtf(ss);

    // one-hot label scan (coalesced, warp-parallel, max-reduce)
    const float* dr = dist + (size_t)srow * 100;
    int cand = -1;
    if (dr[lane] > 0.5f)      cand = lane;
    if (dr[lane + 32] > 0.5f) cand = lane + 32;
    if (dr[lane + 64] > 0.5f) cand = lane + 64;
    if (lane < 4 && dr[lane + 96] > 0.5f) cand = lane + 96;
    #pragma unroll
    for (int o = 16; o; o >>= 1) cand = max(cand, __shfl_xor_sync(0xffffffffu, cand, o));

    // quantize 8 elements: q = round(S*x) = 256*a1 + a2
    float x[8] = {v0.x * rn, v0.y * rn, v0.z * rn, v0.w * rn,
                  v1.x * rn, v1.y * rn, v1.z * rn, v1.w * rn};
    signed char a1[8], a2[8];
    #pragma unroll
    for (int i = 0; i < 8; i++) {
        int q = __float2int_rn(x[i] * 98304.0f);
        q = max(-32639, min(32639, q));    // a1 in [-127,127], a2 in [-128,127]
        int h = (q + 128) >> 8;
        a1[i] = (signed char)h;
        a2[i] = (signed char)(q - (h << 8));
    }
    unsigned char* pr = g_pk + (size_t)row * 1024;
    *(char4*)(pr + lane * 4)             = make_char4(a1[0], a1[1], a1[2], a1[3]);
    *(char4*)(pr + 128 + lane * 4)       = make_char4(a1[4], a1[5], a1[6], a1[7]);
    *(char4*)(pr + 256 + lane * 4)       = make_char4(a2[0], a2[1], a2[2], a2[3]);
    *(char4*)(pr + 384 + lane * 4)       = make_char4(a2[4], a2[5], a2[6], a2[7]);

    if (lane == 0) {
        g_lab[row] = cand;
        g_den[row] = 0.f;
        g_nom[row] = 0.f;
    }
}

// ---------------------------------------------------------------------------
// k_sim: one 128x128 tile per CTA. 16 warps (4 over M x 4 over N), 32x32/warp.
// 2 CTAs/SM at 512 threads -> 32 warps/SM (50% occ). Last CTA reduces.
__global__ void __launch_bounds__(512, 2) k_sim(float* __restrict__ out) {
    extern __shared__ char sm[];
    __shared__ int sLabR[TS], sLabC[TS];
    __shared__ int sLast;
    __shared__ float fpart[16];

    int tid  = threadIdx.x;
    int lane = tid & 31;
    int wid  = tid >> 5;
    int wm   = wid & 3;           // 4 warps over M (32 rows each)
    int wn   = wid >> 2;          // 4 warps over N (32 cols each)

    // decode linear tile id -> (br, bc) with bc >= br (triangular)
    int t = blockIdx.x;
    int br = 0;
    while (t >= (NTILE - br)) { t -= (NTILE - br); br++; }
    int bc = br + t;
    int rowA0 = br * TS;
    int rowB0 = bc * TS;

    if (tid < TS) {
        sLabR[tid] = g_lab[rowA0 + tid];
        sLabC[tid] = g_lab[rowB0 + tid];
    }

    uint32_t smB = smem_u32(sm);

    // chunk -> source byte offsets in the packed row
    // main  (c 0..1): both a1 -> 0,128
    // cross (c 2..5): A = [a1|a2] -> 0,128,256,384 ; B = [a2|a1] -> 256,384,0,128
    auto srcOffA = [](int c) { return (c < 2) ? c * 128 : (c - 2) * 128; };
    auto srcOffB = [](int c) {
        return (c < 2) ? c * 128
             : ((c < 4) ? (c - 2) * 128 + 256 : (c - 4) * 128);
    };

    auto issue = [&](int c, int st) {
        int oA = srcOffA(c), oB = srcOffB(c);
        #pragma unroll
        for (int u = 0; u < 2; u++) {                 // A: 1024 x 16B
            int idx = tid + u * 512, r = idx >> 3, ks = idx & 7;
            cp_async16(smB + st * A_STG + r * SROWB + ks * 16,
                       g_pk + (size_t)(rowA0 + r) * 1024 + oA + ks * 16);
        }
        #pragma unroll
        for (int u = 0; u < 2; u++) {                 // B: 1024 x 16B
            int idx = tid + u * 512, r = idx >> 3, ks = idx & 7;
            cp_async16(smB + B_OFF + st * B_STG + r * SROWB + ks * 16,
                       g_pk + (size_t)(rowB0 + r) * 1024 + oB + ks * 16);
        }
        CP_COMMIT();
    };

    int acc[2][4][4];             // the ONLY accumulator set (32 regs)
    #pragma unroll
    for (int i = 0; i < 2; i++)
        #pragma unroll
        for (int j = 0; j < 4; j++)
            #pragma unroll
            for (int k = 0; k < 4; k++) acc[i][j][k] = 0;

    issue(0, 0);
    issue(1, 1);

    uint32_t aLane = (uint32_t)((wm * 32 + (lane & 15)) * SROWB + (lane >> 4) * 16);
    uint32_t bLane = (uint32_t)(B_OFF + (wn * 32 + (lane & 15)) * SROWB + (lane >> 4) * 16);

    // ---- phase 1: main product a1.a1', chunks 0..1 ----
    #pragma unroll 1
    for (int c = 0; c < 2; c++) {
        int st = c & 1;
        CP_WAIT1();
        __syncthreads();

        uint32_t aBase = smB + st * A_STG + aLane;
        uint32_t bBase = smB + st * B_STG + bLane;
        #pragma unroll
        for (int ks = 0; ks < 4; ks++) {
            uint32_t A[2][4];
            #pragma unroll
            for (int mt = 0; mt < 2; mt++)
                LDSM_X4(A[mt][0], A[mt][1], A[mt][2], A[mt][3],
                        aBase + mt * 16 * SROWB + ks * 32);
            #pragma unroll
            for (int ntp = 0; ntp < 2; ntp++) {
                uint32_t b[4];
                LDSM_X4(b[0], b[1], b[2], b[3], bBase + ntp * 16 * SROWB + ks * 32);
                #pragma unroll
                for (int mt = 0; mt < 2; mt++) {
                    imma_s8(acc[mt][ntp * 2],     A[mt], b[0], b[2]);
                    imma_s8(acc[mt][ntp * 2 + 1], A[mt], b[1], b[3]);
                }
            }
        }
        __syncthreads();
        issue(c + 2, st);
    }

    // ---- fold main: exact s32 -> f32 (|S| <= 4.2e6 < 2^23); reset acc ----
    float accf[2][4][4];
    #pragma unroll
    for (int i = 0; i < 2; i++)
        #pragma unroll
        for (int j = 0; j < 4; j++)
            #pragma unroll
            for (int k = 0; k < 4; k++) {
                accf[i][j][k] = (float)acc[i][j][k] * KC2;
                acc[i][j][k] = 0;
            }

    // ---- phase 2: cross terms a1.a2' + a2.a1', chunks 2..5 ----
    #pragma unroll 1
    for (int c = 2; c < NCH; c++) {
        int st = c & 1;
        CP_WAIT1();
        __syncthreads();

        uint32_t aBase = smB + st * A_STG + aLane;
        uint32_t bBase = smB + st * B_STG + bLane;
        #pragma unroll
        for (int ks = 0; ks < 4; ks++) {
            uint32_t A[2][4];
            #pragma unroll
            for (int mt = 0; mt < 2; mt++)
                LDSM_X4(A[mt][0], A[mt][1], A[mt][2], A[mt][3],
                        aBase + mt * 16 * SROWB + ks * 32);
            #pragma unroll
            for (int ntp = 0; ntp < 2; ntp++) {
                uint32_t b[4];
                LDSM_X4(b[0], b[1], b[2], b[3], bBase + ntp * 16 * SROWB + ks * 32);
                #pragma unroll
                for (int mt = 0; mt < 2; mt++) {
                    imma_s8(acc[mt][ntp * 2],     A[mt], b[0], b[2]);
                    imma_s8(acc[mt][ntp * 2 + 1], A[mt], b[1], b[3]);
                }
            }
        }
        __syncthreads();
        if (c + 2 < NCH) issue(c + 2, st);
        else CP_COMMIT();
    }

    // ---- fold cross: exact s32 -> f32 (|S| <= 8.4e6 < 2^23) ----
    #pragma unroll
    for (int i = 0; i < 2; i++)
        #pragma unroll
        for (int j = 0; j < 4; j++)
            #pragma unroll
            for (int k = 0; k < 4; k++)
                accf[i][j][k] = fmaf((float)acc[i][j][k], KC1, accf[i][j][k]);

    // ---------------- epilogue: count (gr,gc) iff gr<gc, scatter both sides --
    int mrow = lane >> 2;
    int ncol = (lane & 3) * 2;

    float cd[4][2], cm[4][2];
    #pragma unroll
    for (int n8 = 0; n8 < 4; n8++) { cd[n8][0] = cd[n8][1] = 0.f; cm[n8][0] = cm[n8][1] = 0.f; }

    #pragma unroll
    for (int mt = 0; mt < 2; mt++) {
        #pragma unroll
        for (int h = 0; h < 2; h++) {
            int rloc = wm * 32 + mt * 16 + h * 8 + mrow;
            int gr   = rowA0 + rloc;
            int labr = sLabR[rloc];
            float rd = 0.f, rm = 0.f;
            #pragma unroll
            for (int n8 = 0; n8 < 4; n8++) {
                #pragma unroll
                for (int j = 0; j < 2; j++) {
                    int cloc = wn * 32 + n8 * 8 + ncol + j;
                    int gc   = rowB0 + cloc;
                    float s  = accf[mt][n8][h * 2 + j];
                    if (gr < gc) {
                        float e = exp_poly(s);
                        float m = (labr == sLabC[cloc]) ? s : 0.f;
                        rd += e; rm += m;
                        cd[n8][j] += e; cm[n8][j] += m;
                    }
                }
            }
            #pragma unroll
            for (int o = 1; o <= 2; o <<= 1) {
                rd += __shfl_xor_sync(0xffffffffu, rd, o);
                rm += __shfl_xor_sync(0xffffffffu, rm, o);
            }
            if ((lane & 3) == 0) {
                atomicAdd(&g_den[gr], rd);
                atomicAdd(&g_nom[gr], rm);
            }
        }
    }
    #pragma unroll
    for (int n8 = 0; n8 < 4; n8++)
        #pragma unroll
        for (int j = 0; j < 2; j++) {
            #pragma unroll
            for (int o = 4; o <= 16; o <<= 1) {
                cd[n8][j] += __shfl_xor_sync(0xffffffffu, cd[n8][j], o);
                cm[n8][j] += __shfl_xor_sync(0xffffffffu, cm[n8][j], o);
            }
            if (lane < 4) {
                int gc = rowB0 + wn * 32 + n8 * 8 + (lane & 3) * 2 + j;
                atomicAdd(&g_den[gc], cd[n8][j]);
                atomicAdd(&g_nom[gc], cm[n8][j]);
            }
        }

    // ---------------- fused final reduction (last CTA) ----------------------
    __threadfence();              // make this CTA's atomics globally visible
    __syncthreads();
    if (tid == 0) {
        int prev = atomicAdd(&g_ctr, 1);
        sLast = (prev == NTILES - 1) ? 1 : 0;
    }
    __syncthreads();
    if (sLast) {
        __threadfence();
        float s = 0.f;
        #pragma unroll
        for (int i = 0; i < 8; i++) {
            int n = tid + i * 512;
            s += g_nom[n] / g_den[n];
        }
        #pragma unroll
        for (int o = 16; o; o >>= 1) s += __shfl_xor_sync(0xffffffffu, s, o);
        if (lane == 0) fpart[wid] = s;
        __syncthreads();
        if (tid == 0) {
            float tot = 0.f;
            #pragma unroll
            for (int i = 0; i < 16; i++) tot += fpart[i];
            out[0] = tot / 4096.0f;
            g_ctr = 0;            // reset for next graph replay
        }
    }
}

// ---------------------------------------------------------------------------
extern "C" void kernel_launch(void* const* d_in, const int* in_sizes, int n_in,
                              void* d_out, int out_size) {
    const float* zi   = (const float*)d_in[0];
    const float* zj   = (const float*)d_in[1];
    // d_in[2] = z_n is dead code in the reference
    const float* dist = (const float*)d_in[3];
    float* out = (float*)d_out;

    cudaFuncSetAttribute(k_sim, cudaFuncAttributeMaxDynamicSharedMemorySize, SMEM_DYN);

    k_prep<<<512, 256>>>(zi, zj, dist);
    k_sim<<<NTILES, 512, SMEM_DYN>>>(out);
}